// round 7
// baseline (speedup 1.0000x reference)
#include <cuda_runtime.h>

#define NROWS 1024
#define CIN   128
#define COUT  256
#define MEMB  65536
#define PP    8
#define NNEG  32
#define INV_T 1.25f
#define BIGV  1000000000.0f

// ---------------- device scratch (static; no allocation) ----------------
__device__ __align__(16) float g_fn[NROWS * COUT];                         // 1 MB
__device__ __align__(16) float g_Bank2[(size_t)MEMB * COUT];               // 64 MB
__device__ __align__(16) float g_flag2[MEMB];
__device__ __align__(16) float g_pairs[(size_t)NROWS * MEMB];              // 256 MB
__device__ int   g_rndIdx[NROWS * NNEG];
__device__ float g_posHard[NROWS * PP];
__device__ float g_negHard[NROWS * NNEG];
__device__ float g_negRand[NROWS * NNEG];
__device__ float g_posSum[NROWS];
__device__ float g_negSum[NROWS];
__device__ float g_rowLoss[NROWS];
__device__ int   g_idx64;            // 1 if input_index buffer is int64, 0 if int32

// ---------------- helpers ----------------
__device__ __forceinline__ unsigned int ford(float f) {
    unsigned int b = __float_as_uint(f);
    return (b & 0x80000000u) ? ~b : (b | 0x80000000u);
}
__device__ __forceinline__ float iford(unsigned int o) {
    unsigned int b = (o & 0x80000000u) ? (o ^ 0x80000000u) : ~o;
    return __uint_as_float(b);
}
__device__ __forceinline__ long long get_idx(const void* p, int t) {
    if (g_idx64) return ((const long long*)p)[t];
    return (long long)((const int*)p)[t];
}
__device__ __forceinline__ void tf_round(unsigned int& x0, unsigned int& x1, int r) {
    x0 += x1;
    x1 = (x1 << r) | (x1 >> (32 - r));
    x1 ^= x0;
}
// Threefry-2x32-20, key (k0,k1), matches JAX
__device__ __forceinline__ void threefry(unsigned int k0, unsigned int k1,
                                         unsigned int& x0, unsigned int& x1) {
    unsigned int k2 = k0 ^ k1 ^ 0x1BD11BDAu;
    x0 += k0; x1 += k1;
    tf_round(x0,x1,13); tf_round(x0,x1,15); tf_round(x0,x1,26); tf_round(x0,x1,6);
    x0 += k1; x1 += k2 + 1u;
    tf_round(x0,x1,17); tf_round(x0,x1,29); tf_round(x0,x1,16); tf_round(x0,x1,24);
    x0 += k2; x1 += k0 + 2u;
    tf_round(x0,x1,13); tf_round(x0,x1,15); tf_round(x0,x1,26); tf_round(x0,x1,6);
    x0 += k0; x1 += k1 + 3u;
    tf_round(x0,x1,17); tf_round(x0,x1,29); tf_round(x0,x1,16); tf_round(x0,x1,24);
    x0 += k1; x1 += k2 + 4u;
    tf_round(x0,x1,13); tf_round(x0,x1,15); tf_round(x0,x1,26); tf_round(x0,x1,6);
    x0 += k2; x1 += k0 + 5u;
}

// ---------------- 0. classify input_index dtype (int32 vs int64) ----------------
__global__ void k_classify(const unsigned int* __restrict__ p) {
    if (threadIdx.x == 0 && blockIdx.x == 0) {
        int odd_nonzero = 0;
        for (int t = 0; t < 512; t++)
            if (p[2 * t + 1] != 0u) odd_nonzero = 1;
        g_idx64 = odd_nonzero ? 0 : 1;
    }
}

// ---------------- 1. fn = normalize(f @ W^T + b) ----------------
__global__ void k_fn(const float* __restrict__ f, const float* __restrict__ W,
                     const float* __restrict__ bias) {
    int i = blockIdx.x;
    int t = threadIdx.x;              // 256 threads, one per cout
    __shared__ float fr[CIN];
    __shared__ float red[256];
    if (t < CIN) fr[t] = f[i * CIN + t];
    __syncthreads();
    const float* w = W + (size_t)t * CIN;
    float acc = 0.f;
    #pragma unroll 8
    for (int k = 0; k < CIN; k++) acc += fr[k] * w[k];
    acc += bias[t];
    red[t] = acc * acc;
    __syncthreads();
    for (int s = 128; s > 0; s >>= 1) { if (t < s) red[t] += red[t + s]; __syncthreads(); }
    float nrm = sqrtf(red[0]);
    g_fn[i * COUT + t] = acc / nrm;
}

// ---------------- 2. copy Bank -> Bank2, bank_flag -> flag2 ----------------
__global__ void k_copy(const float* __restrict__ Bank, const float* __restrict__ flag) {
    size_t i = (size_t)blockIdx.x * blockDim.x + threadIdx.x;
    size_t stride = (size_t)gridDim.x * blockDim.x;
    const size_t tot4 = (size_t)MEMB * COUT / 4;
    float4* dst = (float4*)g_Bank2;
    const float4* src = (const float4*)Bank;
    for (size_t u = i; u < tot4; u += stride) dst[u] = src[u];
    for (size_t u = i; u < MEMB; u += stride) g_flag2[u] = flag[u];
}

__global__ void k_setflag(const void* __restrict__ idx) {
    int t = blockIdx.x * blockDim.x + threadIdx.x;
    if (t < NROWS) {
        long long v = get_idx(idx, t);
        g_flag2[v] = 1.0f;
    }
}

// ---------------- 3. scatter fn rows into Bank2 (last write wins) ----------------
__global__ void k_scatter(const void* __restrict__ idx) {
    __shared__ long long s[NROWS];
    __shared__ int later;
    int i = blockIdx.x, t = threadIdx.x;   // 256 threads
    for (int u = t; u < NROWS; u += 256) s[u] = get_idx(idx, u);
    if (t == 0) later = 0;
    __syncthreads();
    long long mine = s[i];
    for (int j = i + 1 + t; j < NROWS; j += 256)
        if (s[j] == mine) later = 1;   // benign race (all write 1)
    __syncthreads();
    if (!later) {
        const float* src = g_fn + (size_t)i * COUT;
        float* dst = g_Bank2 + (size_t)mine * COUT;
        if (t < COUT) dst[t] = src[t];
    }
}

// ---------------- 4. rnd_idx: top-32 of threefry uniform per row ----------------
#define CANDCAP 2048
__global__ void k_rnd(const int* __restrict__ label, const int* __restrict__ label_all) {
    int i0 = blockIdx.x;           // handles rows i0 and i0+512
    int t = threadIdx.x;           // 256
    __shared__ unsigned long long cand0[CANDCAP], cand1[CANDCAP];
    __shared__ int cnt0, cnt1;
    __shared__ unsigned long long red[256];
    if (t == 0) { cnt0 = 0; cnt1 = 0; }
    __syncthreads();
    int lab0 = label[i0], lab1 = label[i0 + 512];
    const unsigned int THRESH = 8355840u;   // 2^23 - 32768 -> ~256 cands/row
    for (int j = t; j < MEMB; j += 256) {
        unsigned int x0 = (unsigned int)(i0 * 65536 + j);
        unsigned int x1 = x0 + (1u << 25);
        threefry(0u, 1u, x0, x1);
        unsigned int m0 = x0 >> 9, m1 = x1 >> 9;
        int la = label_all[j];
        float fl = g_flag2[j];
        bool okf = (fl > 0.f);
        if (okf && la != lab0 && m0 >= THRESH) {
            int p = atomicAdd(&cnt0, 1);
            if (p < CANDCAP)
                cand0[p] = ((unsigned long long)m0 << 17) | (unsigned)(0x1FFFF - j);
        }
        if (okf && la != lab1 && m1 >= THRESH) {
            int p = atomicAdd(&cnt1, 1);
            if (p < CANDCAP)
                cand1[p] = ((unsigned long long)m1 << 17) | (unsigned)(0x1FFFF - j);
        }
    }
    __syncthreads();
    for (int half = 0; half < 2; half++) {
        unsigned long long* cand = half ? cand1 : cand0;
        int n = half ? cnt1 : cnt0;
        if (n > CANDCAP) n = CANDCAP;
        int row = half ? (i0 + 512) : i0;
        for (int k = 0; k < NNEG; k++) {
            unsigned long long best = 0;
            for (int u = t; u < n; u += 256) best = best > cand[u] ? best : cand[u];
            red[t] = best;
            __syncthreads();
            for (int s = 128; s > 0; s >>= 1) {
                if (t < s) red[t] = red[t] > red[t + s] ? red[t] : red[t + s];
                __syncthreads();
            }
            best = red[0];
            if (t == 0) {
                int j = 0x1FFFF - (int)(best & 0x1FFFFu);
                g_rndIdx[row * NNEG + k] = (best == 0ull) ? 0 : j;
            }
            for (int u = t; u < n; u += 256) if (cand[u] == best) cand[u] = 0ull;
            __syncthreads();
        }
    }
}

// ---------------- 5. pairs = fn @ Bank2^T (fp32 SGEMM) ----------------
#define BM 128
#define BN 128
#define BKK 16
__global__ void __launch_bounds__(256, 2) k_gemm() {
    __shared__ float As[BKK][BM];
    __shared__ float Bs[BKK][BN];
    int t = threadIdx.x;
    int tx = t & 15, ty = t >> 4;
    const float* A = g_fn + (size_t)blockIdx.y * BM * COUT;
    const float* B = g_Bank2 + (size_t)blockIdx.x * BN * COUT;

    int r0 = t >> 2;                  // 0..63
    int q0 = (t & 3) * 4;             // 0,4,8,12
    int r1 = r0 + 64;

    float acc[8][8];
    #pragma unroll
    for (int r = 0; r < 8; r++)
        #pragma unroll
        for (int c = 0; c < 8; c++) acc[r][c] = 0.f;

    float4 a0 = *(const float4*)(A + (size_t)r0 * COUT + q0);
    float4 a1 = *(const float4*)(A + (size_t)r1 * COUT + q0);
    float4 b0 = *(const float4*)(B + (size_t)r0 * COUT + q0);
    float4 b1 = *(const float4*)(B + (size_t)r1 * COUT + q0);

    for (int kb = 0; kb < COUT; kb += BKK) {
        As[q0 + 0][r0] = a0.x; As[q0 + 1][r0] = a0.y; As[q0 + 2][r0] = a0.z; As[q0 + 3][r0] = a0.w;
        As[q0 + 0][r1] = a1.x; As[q0 + 1][r1] = a1.y; As[q0 + 2][r1] = a1.z; As[q0 + 3][r1] = a1.w;
        Bs[q0 + 0][r0] = b0.x; Bs[q0 + 1][r0] = b0.y; Bs[q0 + 2][r0] = b0.z; Bs[q0 + 3][r0] = b0.w;
        Bs[q0 + 0][r1] = b1.x; Bs[q0 + 1][r1] = b1.y; Bs[q0 + 2][r1] = b1.z; Bs[q0 + 3][r1] = b1.w;
        __syncthreads();
        if (kb + BKK < COUT) {
            int ko = kb + BKK + q0;
            a0 = *(const float4*)(A + (size_t)r0 * COUT + ko);
            a1 = *(const float4*)(A + (size_t)r1 * COUT + ko);
            b0 = *(const float4*)(B + (size_t)r0 * COUT + ko);
            b1 = *(const float4*)(B + (size_t)r1 * COUT + ko);
        }
        #pragma unroll
        for (int kk = 0; kk < BKK; kk++) {
            float ar[8], br[8];
            *(float4*)&ar[0] = *(const float4*)&As[kk][ty * 4];
            *(float4*)&ar[4] = *(const float4*)&As[kk][64 + ty * 4];
            *(float4*)&br[0] = *(const float4*)&Bs[kk][tx * 4];
            *(float4*)&br[4] = *(const float4*)&Bs[kk][64 + tx * 4];
            #pragma unroll
            for (int r = 0; r < 8; r++)
                #pragma unroll
                for (int c = 0; c < 8; c++)
                    acc[r][c] += ar[r] * br[c];
        }
        __syncthreads();
    }

    int colBase = blockIdx.x * BN;
    #pragma unroll
    for (int rg = 0; rg < 2; rg++)
        #pragma unroll
        for (int r = 0; r < 4; r++) {
            int row = blockIdx.y * BM + rg * 64 + ty * 4 + r;
            float* C = g_pairs + (size_t)row * MEMB + colBase;
            int ai = rg * 4 + r;
            float4 v0 = make_float4(acc[ai][0], acc[ai][1], acc[ai][2], acc[ai][3]);
            float4 v1 = make_float4(acc[ai][4], acc[ai][5], acc[ai][6], acc[ai][7]);
            *(float4*)(C + tx * 4) = v0;
            *(float4*)(C + 64 + tx * 4) = v1;
        }
}

// ---------------- 6. per-row selection ----------------
__global__ void __launch_bounds__(128) k_select(const int* __restrict__ label,
                                                const int* __restrict__ label_all) {
    int i = blockIdx.x;
    int t = threadIdx.x;   // 128
    int lab = label[i];
    const float* row = g_pairs + (size_t)i * MEMB;

    unsigned long long nl[NNEG], pl[PP];
    #pragma unroll
    for (int q = 0; q < NNEG; q++) nl[q] = 0ull;
    #pragma unroll
    for (int q = 0; q < PP; q++) pl[q] = 0ull;
    unsigned long long nmin = 0ull, pmin = 0ull;
    int nminp = 0, pminp = 0;
    float psum = 0.f, nsum = 0.f;

    for (int j = t; j < MEMB; j += 128) {
        float v = row[j];
        float fl = g_flag2[j];
        int la = label_all[j];
        if (fl > 0.f) {
            if (la == lab) {
                psum += fl;
                unsigned long long key =
                    ((unsigned long long)ford(-v) << 17) | (unsigned)(0x1FFFF - j);
                if (key > pmin) {
                    pl[pminp] = key;
                    pmin = ~0ull;
                    #pragma unroll
                    for (int q = 0; q < PP; q++)
                        if (pl[q] < pmin) { pmin = pl[q]; pminp = q; }
                }
            } else {
                nsum += fl;
                unsigned long long key =
                    ((unsigned long long)ford(v) << 17) | (unsigned)(0x1FFFF - j);
                if (key > nmin) {
                    nl[nminp] = key;
                    nmin = ~0ull;
                    #pragma unroll
                    for (int q = 0; q < NNEG; q++)
                        if (nl[q] < nmin) { nmin = nl[q]; nminp = q; }
                }
            }
        }
    }

    __shared__ unsigned long long sN[128 * NNEG];   // 32 KB
    __shared__ unsigned long long sP[128 * PP];     // 8 KB
    __shared__ unsigned long long sR[128];
    __shared__ float sF[128];
    #pragma unroll
    for (int q = 0; q < NNEG; q++) sN[t * NNEG + q] = nl[q];
    #pragma unroll
    for (int q = 0; q < PP; q++) sP[t * PP + q] = pl[q];

    sF[t] = psum;
    __syncthreads();
    for (int s = 64; s > 0; s >>= 1) { if (t < s) sF[t] += sF[t + s]; __syncthreads(); }
    if (t == 0) g_posSum[i] = sF[0];
    __syncthreads();
    sF[t] = nsum;
    __syncthreads();
    for (int s = 64; s > 0; s >>= 1) { if (t < s) sF[t] += sF[t + s]; __syncthreads(); }
    if (t == 0) g_negSum[i] = sF[0];
    __syncthreads();

    // top-32 negatives (max pairs value, lower index on ties)
    for (int k = 0; k < NNEG; k++) {
        unsigned long long best = 0ull;
        #pragma unroll
        for (int q = 0; q < NNEG; q++) {
            unsigned long long v = sN[t * NNEG + q];
            best = best > v ? best : v;
        }
        sR[t] = best;
        __syncthreads();
        for (int s = 64; s > 0; s >>= 1) {
            if (t < s) sR[t] = sR[t] > sR[t + s] ? sR[t] : sR[t + s];
            __syncthreads();
        }
        best = sR[0];
        if (t == 0) {
            g_negHard[i * NNEG + k] =
                (best == 0ull) ? -BIGV : iford((unsigned int)(best >> 17));
        }
        #pragma unroll
        for (int q = 0; q < NNEG; q++)
            if (sN[t * NNEG + q] == best) sN[t * NNEG + q] = 0ull;
        __syncthreads();
    }
    // top-8 positives by smallest value (max of ordered(-v))
    for (int k = 0; k < PP; k++) {
        unsigned long long best = 0ull;
        #pragma unroll
        for (int q = 0; q < PP; q++) {
            unsigned long long v = sP[t * PP + q];
            best = best > v ? best : v;
        }
        sR[t] = best;
        __syncthreads();
        for (int s = 64; s > 0; s >>= 1) {
            if (t < s) sR[t] = sR[t] > sR[t + s] ? sR[t] : sR[t + s];
            __syncthreads();
        }
        best = sR[0];
        if (t == 0) {
            g_posHard[i * PP + k] =
                (best == 0ull) ? BIGV : -iford((unsigned int)(best >> 17));
        }
        #pragma unroll
        for (int q = 0; q < PP; q++)
            if (sP[t * PP + q] == best) sP[t * PP + q] = 0ull;
        __syncthreads();
    }
    // gather random negatives
    if (t < NNEG) {
        int idx = g_rndIdx[i * NNEG + t];
        g_negRand[i * NNEG + t] = row[idx];
    }
}

// ---------------- 7a. per-row loss: one thread per (row, p, variant) ----------------
// grid 64 blocks x 256 threads; block handles 16 rows, 16 units per row.
__global__ void __launch_bounds__(256) k_lossA() {
    int t = threadIdx.x;
    int r = t >> 4;                 // local row 0..15
    int u = t & 15;                 // unit: p = u&7, variant = u>>3
    int i = blockIdx.x * 16 + r;
    int p = u & 7;
    int variant = u >> 3;

    float res = 0.f;
    bool valid = (g_posSum[i] >= (float)PP) && (g_negSum[i] >= (float)NNEG);
    if (valid) {
        float pv = g_posHard[i * PP + p] * INV_T;
        const float* neg = variant ? (g_negRand + i * NNEG) : (g_negHard + i * NNEG);
        float m = pv;
        float nv[NNEG];
        #pragma unroll
        for (int k = 0; k < NNEG; k++) {
            nv[k] = neg[k] * INV_T;
            m = fmaxf(m, nv[k]);
        }
        float s = expf(pv - m);
        #pragma unroll
        for (int k = 0; k < NNEG; k++) s += expf(nv[k] - m);
        res = logf(s) + m - pv;
    }

    __shared__ float sArr[256];
    sArr[t] = res;
    __syncthreads();
    #pragma unroll
    for (int s = 8; s > 0; s >>= 1) {
        if (u < s) sArr[t] += sArr[t + s];
        __syncthreads();
    }
    if (u == 0) g_rowLoss[i] = sArr[t];
}

// ---------------- 7b. final scalar reduction ----------------
__global__ void __launch_bounds__(256) k_lossB(float* __restrict__ out) {
    int t = threadIdx.x;   // 256 threads, 4 rows each
    float acc = 0.f, w = 0.f;
    #pragma unroll
    for (int k = 0; k < 4; k++) {
        int i = t + 256 * k;
        bool valid = (g_posSum[i] >= (float)PP) && (g_negSum[i] >= (float)NNEG);
        if (valid) { acc += g_rowLoss[i]; w += 1.f; }
    }
    __shared__ float sn[256];
    __shared__ float sw[256];
    sn[t] = acc; sw[t] = w;
    __syncthreads();
    for (int s = 128; s > 0; s >>= 1) {
        if (t < s) { sn[t] += sn[t + s]; sw[t] += sw[t + s]; }
        __syncthreads();
    }
    if (t == 0) {
        float den = sw[0] * (2.0f * PP);
        out[0] = (den > 0.f) ? (sn[0] / den) : 0.f;
    }
}

// ---------------- launch ----------------
extern "C" void kernel_launch(void* const* d_in, const int* in_sizes, int n_in,
                              void* d_out, int out_size) {
    const float* f          = (const float*)d_in[0];
    const float* W          = (const float*)d_in[1];
    const float* bias       = (const float*)d_in[2];
    const float* Bank       = (const float*)d_in[3];
    const float* bank_flag  = (const float*)d_in[4];
    const int*   label      = (const int*)d_in[5];
    const void*  input_idx  = d_in[6];
    const int*   label_all  = (const int*)d_in[7];
    float* out = (float*)d_out;

    k_classify<<<1, 32>>>((const unsigned int*)input_idx);
    k_fn<<<NROWS, 256>>>(f, W, bias);
    k_copy<<<4096, 256>>>(Bank, bank_flag);
    k_setflag<<<4, 256>>>(input_idx);
    k_scatter<<<NROWS, 256>>>(input_idx);
    k_rnd<<<512, 256>>>(label, label_all);
    k_gemm<<<dim3(MEMB / BN, NROWS / BM), 256>>>();
    k_select<<<NROWS, 128>>>(label, label_all);
    k_lossA<<<64, 256>>>();
    k_lossB<<<1, 256>>>(out);
}

// round 11
// speedup vs baseline: 1.0810x; 1.0810x over previous
#include <cuda_runtime.h>
#include <cuda_bf16.h>

#define NROWS 1024
#define CIN   128
#define COUT  256
#define MEMB  65536
#define PP    8
#define NNEG  32
#define INV_T 1.25f
#define BIGV  1000000000.0f

// ---------------- device scratch (static; no allocation) ----------------
__device__ __align__(16) float g_fn[NROWS * COUT];                         // 1 MB
__device__ __align__(16) float g_Bank2[(size_t)MEMB * COUT];               // 64 MB
__device__ __align__(16) float g_flag2[MEMB];
__device__ __align__(16) float g_pairs[(size_t)NROWS * MEMB];              // 256 MB
__device__ __align__(16) __nv_bfloat16 g_AH[NROWS * COUT];
__device__ __align__(16) __nv_bfloat16 g_AL[NROWS * COUT];
__device__ __align__(16) __nv_bfloat16 g_BH[(size_t)MEMB * COUT];          // 32 MB
__device__ __align__(16) __nv_bfloat16 g_BL[(size_t)MEMB * COUT];          // 32 MB
__device__ int   g_rndIdx[NROWS * NNEG];
__device__ float g_posHard[NROWS * PP];
__device__ float g_negHard[NROWS * NNEG];
__device__ float g_negRand[NROWS * NNEG];
__device__ float g_posSum[NROWS];
__device__ float g_negSum[NROWS];
__device__ float g_rowLoss[NROWS];
__device__ int   g_idx64;            // 1 if input_index buffer is int64, 0 if int32

// ---------------- helpers ----------------
__device__ __forceinline__ unsigned int ford(float f) {
    unsigned int b = __float_as_uint(f);
    return (b & 0x80000000u) ? ~b : (b | 0x80000000u);
}
__device__ __forceinline__ float iford(unsigned int o) {
    unsigned int b = (o & 0x80000000u) ? (o ^ 0x80000000u) : ~o;
    return __uint_as_float(b);
}
__device__ __forceinline__ long long get_idx(const void* p, int t) {
    if (g_idx64) return ((const long long*)p)[t];
    return (long long)((const int*)p)[t];
}
__device__ __forceinline__ void tf_round(unsigned int& x0, unsigned int& x1, int r) {
    x0 += x1;
    x1 = (x1 << r) | (x1 >> (32 - r));
    x1 ^= x0;
}
// Threefry-2x32-20, key (k0,k1), matches JAX
__device__ __forceinline__ void threefry(unsigned int k0, unsigned int k1,
                                         unsigned int& x0, unsigned int& x1) {
    unsigned int k2 = k0 ^ k1 ^ 0x1BD11BDAu;
    x0 += k0; x1 += k1;
    tf_round(x0,x1,13); tf_round(x0,x1,15); tf_round(x0,x1,26); tf_round(x0,x1,6);
    x0 += k1; x1 += k2 + 1u;
    tf_round(x0,x1,17); tf_round(x0,x1,29); tf_round(x0,x1,16); tf_round(x0,x1,24);
    x0 += k2; x1 += k0 + 2u;
    tf_round(x0,x1,13); tf_round(x0,x1,15); tf_round(x0,x1,26); tf_round(x0,x1,6);
    x0 += k0; x1 += k1 + 3u;
    tf_round(x0,x1,17); tf_round(x0,x1,29); tf_round(x0,x1,16); tf_round(x0,x1,24);
    x0 += k1; x1 += k2 + 4u;
    tf_round(x0,x1,13); tf_round(x0,x1,15); tf_round(x0,x1,26); tf_round(x0,x1,6);
    x0 += k2; x1 += k0 + 5u;
}

__device__ __forceinline__ void mma_bf16(float* c, const unsigned int* a, const unsigned int* b) {
    asm volatile(
        "mma.sync.aligned.m16n8k16.row.col.f32.bf16.bf16.f32 "
        "{%0,%1,%2,%3}, {%4,%5,%6,%7}, {%8,%9}, {%0,%1,%2,%3};"
        : "+f"(c[0]), "+f"(c[1]), "+f"(c[2]), "+f"(c[3])
        : "r"(a[0]), "r"(a[1]), "r"(a[2]), "r"(a[3]), "r"(b[0]), "r"(b[1]));
}

// ---------------- 0. classify input_index dtype (int32 vs int64) ----------------
__global__ void k_classify(const unsigned int* __restrict__ p) {
    if (threadIdx.x == 0 && blockIdx.x == 0) {
        int odd_nonzero = 0;
        for (int t = 0; t < 512; t++)
            if (p[2 * t + 1] != 0u) odd_nonzero = 1;
        g_idx64 = odd_nonzero ? 0 : 1;
    }
}

// ---------------- 1. fn = normalize(f @ W^T + b) ----------------
__global__ void k_fn(const float* __restrict__ f, const float* __restrict__ W,
                     const float* __restrict__ bias) {
    int i = blockIdx.x;
    int t = threadIdx.x;              // 256 threads, one per cout
    __shared__ float fr[CIN];
    __shared__ float red[256];
    if (t < CIN) fr[t] = f[i * CIN + t];
    __syncthreads();
    const float* w = W + (size_t)t * CIN;
    float acc = 0.f;
    #pragma unroll 8
    for (int k = 0; k < CIN; k++) acc += fr[k] * w[k];
    acc += bias[t];
    red[t] = acc * acc;
    __syncthreads();
    for (int s = 128; s > 0; s >>= 1) { if (t < s) red[t] += red[t + s]; __syncthreads(); }
    float nrm = sqrtf(red[0]);
    g_fn[i * COUT + t] = acc / nrm;
}

// ---------------- 2. copy Bank -> Bank2, bank_flag -> flag2 ----------------
__global__ void k_copy(const float* __restrict__ Bank, const float* __restrict__ flag) {
    size_t i = (size_t)blockIdx.x * blockDim.x + threadIdx.x;
    size_t stride = (size_t)gridDim.x * blockDim.x;
    const size_t tot4 = (size_t)MEMB * COUT / 4;
    float4* dst = (float4*)g_Bank2;
    const float4* src = (const float4*)Bank;
    for (size_t u = i; u < tot4; u += stride) dst[u] = src[u];
    for (size_t u = i; u < MEMB; u += stride) g_flag2[u] = flag[u];
}

__global__ void k_setflag(const void* __restrict__ idx) {
    int t = blockIdx.x * blockDim.x + threadIdx.x;
    if (t < NROWS) {
        long long v = get_idx(idx, t);
        g_flag2[v] = 1.0f;
    }
}

// ---------------- 3. scatter fn rows into Bank2 (last write wins) ----------------
__global__ void k_scatter(const void* __restrict__ idx) {
    __shared__ long long s[NROWS];
    __shared__ int later;
    int i = blockIdx.x, t = threadIdx.x;   // 256 threads
    for (int u = t; u < NROWS; u += 256) s[u] = get_idx(idx, u);
    if (t == 0) later = 0;
    __syncthreads();
    long long mine = s[i];
    for (int j = i + 1 + t; j < NROWS; j += 256)
        if (s[j] == mine) later = 1;   // benign race (all write 1)
    __syncthreads();
    if (!later) {
        const float* src = g_fn + (size_t)i * COUT;
        float* dst = g_Bank2 + (size_t)mine * COUT;
        if (t < COUT) dst[t] = src[t];
    }
}

// ---------------- 3b. split fp32 -> bf16 hi/lo ----------------
__global__ void k_cvtA() {
    int i = blockIdx.x * 256 + threadIdx.x;   // 1024 blocks
    float x = g_fn[i];
    __nv_bfloat16 h = __float2bfloat16(x);
    g_AH[i] = h;
    g_AL[i] = __float2bfloat16(x - __bfloat162float(h));
}
__global__ void k_cvtB() {
    size_t i = (size_t)blockIdx.x * blockDim.x + threadIdx.x;
    size_t stride = (size_t)gridDim.x * blockDim.x;
    const size_t tot4 = (size_t)MEMB * COUT / 4;
    for (size_t u = i; u < tot4; u += stride) {
        float4 v = ((const float4*)g_Bank2)[u];
        __nv_bfloat16 h0 = __float2bfloat16(v.x);
        __nv_bfloat16 h1 = __float2bfloat16(v.y);
        __nv_bfloat16 h2 = __float2bfloat16(v.z);
        __nv_bfloat16 h3 = __float2bfloat16(v.w);
        __nv_bfloat16 l0 = __float2bfloat16(v.x - __bfloat162float(h0));
        __nv_bfloat16 l1 = __float2bfloat16(v.y - __bfloat162float(h1));
        __nv_bfloat16 l2 = __float2bfloat16(v.z - __bfloat162float(h2));
        __nv_bfloat16 l3 = __float2bfloat16(v.w - __bfloat162float(h3));
        __nv_bfloat162* dh = (__nv_bfloat162*)g_BH + 2 * u;
        __nv_bfloat162* dl = (__nv_bfloat162*)g_BL + 2 * u;
        dh[0] = __nv_bfloat162(h0, h1); dh[1] = __nv_bfloat162(h2, h3);
        dl[0] = __nv_bfloat162(l0, l1); dl[1] = __nv_bfloat162(l2, l3);
    }
}

// ---------------- 4. rnd_idx: top-32 of threefry uniform per row ----------------
#define CANDCAP 2048
__global__ void k_rnd(const int* __restrict__ label, const int* __restrict__ label_all) {
    int i0 = blockIdx.x;           // handles rows i0 and i0+512
    int t = threadIdx.x;           // 256
    __shared__ unsigned long long cand0[CANDCAP], cand1[CANDCAP];
    __shared__ int cnt0, cnt1;
    __shared__ unsigned long long red[256];
    if (t == 0) { cnt0 = 0; cnt1 = 0; }
    __syncthreads();
    int lab0 = label[i0], lab1 = label[i0 + 512];
    const unsigned int THRESH = 8355840u;   // 2^23 - 32768 -> ~256 cands/row
    for (int j = t; j < MEMB; j += 256) {
        unsigned int x0 = (unsigned int)(i0 * 65536 + j);
        unsigned int x1 = x0 + (1u << 25);
        threefry(0u, 1u, x0, x1);
        unsigned int m0 = x0 >> 9, m1 = x1 >> 9;
        int la = label_all[j];
        float fl = g_flag2[j];
        bool okf = (fl > 0.f);
        if (okf && la != lab0 && m0 >= THRESH) {
            int p = atomicAdd(&cnt0, 1);
            if (p < CANDCAP)
                cand0[p] = ((unsigned long long)m0 << 17) | (unsigned)(0x1FFFF - j);
        }
        if (okf && la != lab1 && m1 >= THRESH) {
            int p = atomicAdd(&cnt1, 1);
            if (p < CANDCAP)
                cand1[p] = ((unsigned long long)m1 << 17) | (unsigned)(0x1FFFF - j);
        }
    }
    __syncthreads();
    for (int half = 0; half < 2; half++) {
        unsigned long long* cand = half ? cand1 : cand0;
        int n = half ? cnt1 : cnt0;
        if (n > CANDCAP) n = CANDCAP;
        int row = half ? (i0 + 512) : i0;
        for (int k = 0; k < NNEG; k++) {
            unsigned long long best = 0;
            for (int u = t; u < n; u += 256) best = best > cand[u] ? best : cand[u];
            red[t] = best;
            __syncthreads();
            for (int s = 128; s > 0; s >>= 1) {
                if (t < s) red[t] = red[t] > red[t + s] ? red[t] : red[t + s];
                __syncthreads();
            }
            best = red[0];
            if (t == 0) {
                int j = 0x1FFFF - (int)(best & 0x1FFFFu);
                g_rndIdx[row * NNEG + k] = (best == 0ull) ? 0 : j;
            }
            for (int u = t; u < n; u += 256) if (cand[u] == best) cand[u] = 0ull;
            __syncthreads();
        }
    }
}

// ---------------- 5. pairs = fn @ Bank2^T via split-bf16 tensor cores ----------------
// C = AH*BH + AH*BL + AL*BH  (AL*BL dropped, ~2^-18 relative)
#define GBM 128
#define GBN 64
#define GBK 32
#define SSTR 40   // smem k-stride in bf16 elems (conflict-free for frag loads)
__global__ void __launch_bounds__(256) k_gemm_mma() {
    __shared__ __nv_bfloat16 sAH[GBM * SSTR], sAL[GBM * SSTR];
    __shared__ __nv_bfloat16 sBH[GBN * SSTR], sBL[GBN * SSTR];
    int t = threadIdx.x;
    int lane = t & 31, wid = t >> 5;
    int wm = wid & 3, wn = wid >> 2;     // warps 4x2 -> warp tile 32x32
    int g = lane >> 2, tig = lane & 3;
    int mBase = blockIdx.y * GBM;
    int nBase = blockIdx.x * GBN;

    const __nv_bfloat16* gAH = g_AH + (size_t)mBase * COUT;
    const __nv_bfloat16* gAL = g_AL + (size_t)mBase * COUT;
    const __nv_bfloat16* gBH = g_BH + (size_t)nBase * COUT;
    const __nv_bfloat16* gBL = g_BL + (size_t)nBase * COUT;

    float acc[2][4][4];
    #pragma unroll
    for (int mt = 0; mt < 2; mt++)
        #pragma unroll
        for (int nt = 0; nt < 4; nt++)
            #pragma unroll
            for (int q = 0; q < 4; q++) acc[mt][nt][q] = 0.f;

    for (int kb = 0; kb < COUT; kb += GBK) {
        // stage A tile 128x32 (hi+lo): 1024 uint2 units, 4 per thread
        #pragma unroll
        for (int q = 0; q < 4; q++) {
            int unit = t + 256 * q;
            int row = unit >> 3, ug = unit & 7;
            size_t go = (size_t)row * COUT + kb + ug * 4;
            int so = row * SSTR + ug * 4;
            *(uint2*)&sAH[so] = *(const uint2*)&gAH[go];
            *(uint2*)&sAL[so] = *(const uint2*)&gAL[go];
        }
        // stage B tile 64x32 (hi+lo): 512 units, 2 per thread
        #pragma unroll
        for (int q = 0; q < 2; q++) {
            int unit = t + 256 * q;
            int row = unit >> 3, ug = unit & 7;
            size_t go = (size_t)row * COUT + kb + ug * 4;
            int so = row * SSTR + ug * 4;
            *(uint2*)&sBH[so] = *(const uint2*)&gBH[go];
            *(uint2*)&sBL[so] = *(const uint2*)&gBL[go];
        }
        __syncthreads();
        #pragma unroll
        for (int kk = 0; kk < GBK; kk += 16) {
            unsigned int ah[2][4], al[2][4], bh[4][2], bl[4][2];
            #pragma unroll
            for (int mt = 0; mt < 2; mt++) {
                int r0 = wm * 32 + mt * 16 + g;
                int b0 = r0 * SSTR + kk + 2 * tig;
                int b1 = (r0 + 8) * SSTR + kk + 2 * tig;
                ah[mt][0] = *(unsigned int*)&sAH[b0];
                ah[mt][1] = *(unsigned int*)&sAH[b1];
                ah[mt][2] = *(unsigned int*)&sAH[b0 + 8];
                ah[mt][3] = *(unsigned int*)&sAH[b1 + 8];
                al[mt][0] = *(unsigned int*)&sAL[b0];
                al[mt][1] = *(unsigned int*)&sAL[b1];
                al[mt][2] = *(unsigned int*)&sAL[b0 + 8];
                al[mt][3] = *(unsigned int*)&sAL[b1 + 8];
            }
            #pragma unroll
            for (int nt = 0; nt < 4; nt++) {
                int n0 = wn * 32 + nt * 8 + g;
                int bb = n0 * SSTR + kk + 2 * tig;
                bh[nt][0] = *(unsigned int*)&sBH[bb];
                bh[nt][1] = *(unsigned int*)&sBH[bb + 8];
                bl[nt][0] = *(unsigned int*)&sBL[bb];
                bl[nt][1] = *(unsigned int*)&sBL[bb + 8];
            }
            #pragma unroll
            for (int mt = 0; mt < 2; mt++)
                #pragma unroll
                for (int nt = 0; nt < 4; nt++) {
                    mma_bf16(acc[mt][nt], ah[mt], bh[nt]);
                    mma_bf16(acc[mt][nt], ah[mt], bl[nt]);
                    mma_bf16(acc[mt][nt], al[mt], bh[nt]);
                }
        }
        __syncthreads();
    }

    // epilogue: write 128x64 fp32 tile
    #pragma unroll
    for (int mt = 0; mt < 2; mt++) {
        int r0 = mBase + wm * 32 + mt * 16 + g;
        float* C0 = g_pairs + (size_t)r0 * MEMB;
        float* C1 = g_pairs + (size_t)(r0 + 8) * MEMB;
        #pragma unroll
        for (int nt = 0; nt < 4; nt++) {
            int c0 = nBase + wn * 32 + nt * 8 + 2 * tig;
            float2 v0 = make_float2(acc[mt][nt][0], acc[mt][nt][1]);
            float2 v1 = make_float2(acc[mt][nt][2], acc[mt][nt][3]);
            *(float2*)&C0[c0] = v0;
            *(float2*)&C1[c0] = v1;
        }
    }
}

// ---------------- 6. per-row selection ----------------
__global__ void __launch_bounds__(128) k_select(const int* __restrict__ label,
                                                const int* __restrict__ label_all) {
    int i = blockIdx.x;
    int t = threadIdx.x;   // 128
    int lab = label[i];
    const float* row = g_pairs + (size_t)i * MEMB;

    unsigned long long nl[NNEG], pl[PP];
    #pragma unroll
    for (int q = 0; q < NNEG; q++) nl[q] = 0ull;
    #pragma unroll
    for (int q = 0; q < PP; q++) pl[q] = 0ull;
    unsigned long long nmin = 0ull, pmin = 0ull;
    int nminp = 0, pminp = 0;
    float psum = 0.f, nsum = 0.f;

    for (int j = t; j < MEMB; j += 128) {
        float v = row[j];
        float fl = g_flag2[j];
        int la = label_all[j];
        if (fl > 0.f) {
            if (la == lab) {
                psum += fl;
                unsigned long long key =
                    ((unsigned long long)ford(-v) << 17) | (unsigned)(0x1FFFF - j);
                if (key > pmin) {
                    pl[pminp] = key;
                    pmin = ~0ull;
                    #pragma unroll
                    for (int q = 0; q < PP; q++)
                        if (pl[q] < pmin) { pmin = pl[q]; pminp = q; }
                }
            } else {
                nsum += fl;
                unsigned long long key =
                    ((unsigned long long)ford(v) << 17) | (unsigned)(0x1FFFF - j);
                if (key > nmin) {
                    nl[nminp] = key;
                    nmin = ~0ull;
                    #pragma unroll
                    for (int q = 0; q < NNEG; q++)
                        if (nl[q] < nmin) { nmin = nl[q]; nminp = q; }
                }
            }
        }
    }

    __shared__ unsigned long long sN[128 * NNEG];   // 32 KB
    __shared__ unsigned long long sP[128 * PP];     // 8 KB
    __shared__ unsigned long long sR[128];
    __shared__ float sF[128];
    #pragma unroll
    for (int q = 0; q < NNEG; q++) sN[t * NNEG + q] = nl[q];
    #pragma unroll
    for (int q = 0; q < PP; q++) sP[t * PP + q] = pl[q];

    sF[t] = psum;
    __syncthreads();
    for (int s = 64; s > 0; s >>= 1) { if (t < s) sF[t] += sF[t + s]; __syncthreads(); }
    if (t == 0) g_posSum[i] = sF[0];
    __syncthreads();
    sF[t] = nsum;
    __syncthreads();
    for (int s = 64; s > 0; s >>= 1) { if (t < s) sF[t] += sF[t + s]; __syncthreads(); }
    if (t == 0) g_negSum[i] = sF[0];
    __syncthreads();

    // top-32 negatives (max pairs value, lower index on ties)
    for (int k = 0; k < NNEG; k++) {
        unsigned long long best = 0ull;
        #pragma unroll
        for (int q = 0; q < NNEG; q++) {
            unsigned long long v = sN[t * NNEG + q];
            best = best > v ? best : v;
        }
        sR[t] = best;
        __syncthreads();
        for (int s = 64; s > 0; s >>= 1) {
            if (t < s) sR[t] = sR[t] > sR[t + s] ? sR[t] : sR[t + s];
            __syncthreads();
        }
        best = sR[0];
        if (t == 0) {
            g_negHard[i * NNEG + k] =
                (best == 0ull) ? -BIGV : iford((unsigned int)(best >> 17));
        }
        #pragma unroll
        for (int q = 0; q < NNEG; q++)
            if (sN[t * NNEG + q] == best) sN[t * NNEG + q] = 0ull;
        __syncthreads();
    }
    // top-8 positives by smallest value (max of ordered(-v))
    for (int k = 0; k < PP; k++) {
        unsigned long long best = 0ull;
        #pragma unroll
        for (int q = 0; q < PP; q++) {
            unsigned long long v = sP[t * PP + q];
            best = best > v ? best : v;
        }
        sR[t] = best;
        __syncthreads();
        for (int s = 64; s > 0; s >>= 1) {
            if (t < s) sR[t] = sR[t] > sR[t + s] ? sR[t] : sR[t + s];
            __syncthreads();
        }
        best = sR[0];
        if (t == 0) {
            g_posHard[i * PP + k] =
                (best == 0ull) ? BIGV : -iford((unsigned int)(best >> 17));
        }
        #pragma unroll
        for (int q = 0; q < PP; q++)
            if (sP[t * PP + q] == best) sP[t * PP + q] = 0ull;
        __syncthreads();
    }
    // gather random negatives
    if (t < NNEG) {
        int idx = g_rndIdx[i * NNEG + t];
        g_negRand[i * NNEG + t] = row[idx];
    }
}

// ---------------- 7a. per-row loss ----------------
__global__ void __launch_bounds__(256) k_lossA() {
    int t = threadIdx.x;
    int r = t >> 4;
    int u = t & 15;
    int i = blockIdx.x * 16 + r;
    int p = u & 7;
    int variant = u >> 3;

    float res = 0.f;
    bool valid = (g_posSum[i] >= (float)PP) && (g_negSum[i] >= (float)NNEG);
    if (valid) {
        float pv = g_posHard[i * PP + p] * INV_T;
        const float* neg = variant ? (g_negRand + i * NNEG) : (g_negHard + i * NNEG);
        float m = pv;
        float nv[NNEG];
        #pragma unroll
        for (int k = 0; k < NNEG; k++) {
            nv[k] = neg[k] * INV_T;
            m = fmaxf(m, nv[k]);
        }
        float s = expf(pv - m);
        #pragma unroll
        for (int k = 0; k < NNEG; k++) s += expf(nv[k] - m);
        res = logf(s) + m - pv;
    }

    __shared__ float sArr[256];
    sArr[t] = res;
    __syncthreads();
    #pragma unroll
    for (int s = 8; s > 0; s >>= 1) {
        if (u < s) sArr[t] += sArr[t + s];
        __syncthreads();
    }
    if (u == 0) g_rowLoss[i] = sArr[t];
}

// ---------------- 7b. final scalar reduction ----------------
__global__ void __launch_bounds__(256) k_lossB(float* __restrict__ out) {
    int t = threadIdx.x;
    float acc = 0.f, w = 0.f;
    #pragma unroll
    for (int k = 0; k < 4; k++) {
        int i = t + 256 * k;
        bool valid = (g_posSum[i] >= (float)PP) && (g_negSum[i] >= (float)NNEG);
        if (valid) { acc += g_rowLoss[i]; w += 1.f; }
    }
    __shared__ float sn[256];
    __shared__ float sw[256];
    sn[t] = acc; sw[t] = w;
    __syncthreads();
    for (int s = 128; s > 0; s >>= 1) {
        if (t < s) { sn[t] += sn[t + s]; sw[t] += sw[t + s]; }
        __syncthreads();
    }
    if (t == 0) {
        float den = sw[0] * (2.0f * PP);
        out[0] = (den > 0.f) ? (sn[0] / den) : 0.f;
    }
}

// ---------------- launch ----------------
extern "C" void kernel_launch(void* const* d_in, const int* in_sizes, int n_in,
                              void* d_out, int out_size) {
    const float* f          = (const float*)d_in[0];
    const float* W          = (const float*)d_in[1];
    const float* bias       = (const float*)d_in[2];
    const float* Bank       = (const float*)d_in[3];
    const float* bank_flag  = (const float*)d_in[4];
    const int*   label      = (const int*)d_in[5];
    const void*  input_idx  = d_in[6];
    const int*   label_all  = (const int*)d_in[7];
    float* out = (float*)d_out;

    k_classify<<<1, 32>>>((const unsigned int*)input_idx);
    k_fn<<<NROWS, 256>>>(f, W, bias);
    k_copy<<<4096, 256>>>(Bank, bank_flag);
    k_setflag<<<4, 256>>>(input_idx);
    k_scatter<<<NROWS, 256>>>(input_idx);
    k_cvtA<<<NROWS, 256>>>();
    k_cvtB<<<8192, 256>>>();
    k_rnd<<<512, 256>>>(label, label_all);
    k_gemm_mma<<<dim3(MEMB / GBN, NROWS / GBM), 256>>>();
    k_select<<<NROWS, 128>>>(label, label_all);
    k_lossA<<<64, 256>>>();
    k_lossB<<<1, 256>>>(out);
}